// round 10
// baseline (speedup 1.0000x reference)
#include <cuda_runtime.h>
#include <cstdint>
#include <cstddef>

#define N_NODES 50000
#define N_EDGES 800000
#define N_LINE  800000
#define D 128
#define NL 3

// ---------------- scratch (static device globals; no allocations) ----------------
__device__ float g_nf0[(size_t)N_NODES * D];
__device__ float g_nf1[(size_t)N_NODES * D];
__device__ float g_ef0[(size_t)N_EDGES * D];
__device__ float g_ef1[(size_t)N_EDGES * D];
__device__ float g_an [(size_t)N_NODES * D];   // zero at entry/exit of every call
__device__ float g_a1n[(size_t)N_NODES * D];
__device__ float g_ae0[(size_t)N_EDGES * D];   // ping-pong edge agg buffers
__device__ float g_a1e0[(size_t)N_EDGES * D];
__device__ float g_ae1[(size_t)N_EDGES * D];
__device__ float g_a1e1[(size_t)N_EDGES * D];
__device__ unsigned int g_pool[2 * D];
// packed weights: 20 matrices x [hi 128x64 u32 | lo 128x64 u32]
__device__ uint32_t g_wpk[20 * 16384];

// ---------------- gather + scatter-add (one warp per edge-row, float4 RED) -------
__global__ void scatter_add_k(const float* __restrict__ src, float* __restrict__ dst,
                              const int* __restrict__ gidx, const int* __restrict__ sidx,
                              int count)
{
    int lane  = threadIdx.x & 31;
    int warp  = (blockIdx.x * blockDim.x + threadIdx.x) >> 5;
    int nwarp = (gridDim.x * blockDim.x) >> 5;
    for (int e = warp; e < count; e += nwarp) {
        int g = gidx[e];
        int s = sidx[e];
        float4 v = *((const float4*)(src + (size_t)g * D) + lane);
        atomicAdd((float4*)(dst + (size_t)s * D) + lane, v);
    }
}

// ============================ bf16 split helpers =================================
__device__ __forceinline__ uint32_t packbf(float hi_el, float lo_el) {
    uint32_t r;
    asm("cvt.rn.bf16x2.f32 %0, %1, %2;" : "=r"(r) : "f"(hi_el), "f"(lo_el));
    return r;
}
__device__ __forceinline__ float bf_lo(uint32_t u) { return __uint_as_float(u << 16); }
__device__ __forceinline__ float bf_hi(uint32_t u) { return __uint_as_float(u & 0xFFFF0000u); }

__device__ __forceinline__ void mma16(float* d, uint32_t a0, uint32_t a1, uint32_t a2,
                                      uint32_t a3, uint32_t b0, uint32_t b1)
{
    asm volatile(
        "mma.sync.aligned.m16n8k16.row.col.f32.bf16.bf16.f32 "
        "{%0,%1,%2,%3}, {%4,%5,%6,%7}, {%8,%9}, {%0,%1,%2,%3};"
        : "+f"(d[0]), "+f"(d[1]), "+f"(d[2]), "+f"(d[3])
        : "r"(a0), "r"(a1), "r"(a2), "r"(a3), "r"(b0), "r"(b1));
}

__device__ __forceinline__ void ldm4(uint32_t* r, uint32_t addr) {
    asm volatile("ldmatrix.sync.aligned.m8n8.x4.shared.b16 {%0,%1,%2,%3}, [%4];"
                 : "=r"(r[0]), "=r"(r[1]), "=r"(r[2]), "=r"(r[3]) : "r"(addr));
}
__device__ __forceinline__ void cp16(uint32_t dst, const void* src) {
    asm volatile("cp.async.ca.shared.global [%0], [%1], 16;" :: "r"(dst), "l"(src));
}
#define CP_COMMIT() asm volatile("cp.async.commit_group;" ::: "memory")
#define CP_WAIT0()  asm volatile("cp.async.wait_group 0;" ::: "memory")

// ---------------- weight pre-pack (single launch, all 20 matrices) ---------------
__global__ void wprep_all_k(const float* __restrict__ nWc, const float* __restrict__ nWn,
                            const float* __restrict__ nWe, const float* __restrict__ eWc,
                            const float* __restrict__ eWn, const float* __restrict__ eWe,
                            const float* __restrict__ Wno, const float* __restrict__ Weo,
                            uint32_t* __restrict__ out)
{
    int i = blockIdx.x * blockDim.x + threadIdx.x;
    if (i >= 20 * 8192) return;
    int m = i >> 13, r = i & 8191;
    int n = r >> 6, k2 = r & 63;
    const float* srcs[8] = { nWc, nWn, nWe, eWc, eWn, eWe, Wno, Weo };
    int grp = (m < 18) ? (m / 3) : (m - 18 + 6);
    int loc = (m < 18) ? (m % 3) : 0;
    const float* w = srcs[grp] + (size_t)loc * 16384;
    float x0 = w[(2 * k2) * D + n];
    float x1 = w[(2 * k2 + 1) * D + n];
    uint32_t hi = packbf(x1, x0);
    float r0 = x0 - bf_lo(hi);
    float r1 = x1 - bf_hi(hi);
    uint32_t lo = packbf(r1, r0);
    out[(size_t)m * 16384 + n * 64 + k2]        = hi;
    out[(size_t)m * 16384 + 8192 + n * 64 + k2] = lo;
}

// SMEM (dynamic, 82944 B):
//   [0..512) bias, [512..1024) inv
//   [1024..) two 40960B stages: AsH 128x20u32 | AsL | BsH 128x20u32 | BsL
//   epilogue staging 128x132 f (67584 B) aliases the stage region.
#define SM_TOTAL 82944
#define STG_BYTES 40960

// ========== bf16x3 tensor-core GEMM, cp.async + ldmatrix 2-stage pipeline ========
// nsrc==3 layer GEMMs additionally re-zero their consumed aggregation slices.
__global__ void __launch_bounds__(256, 2) tc_gemm_k(
    const float* __restrict__ x0, const float* __restrict__ x1, const float* __restrict__ x2,
    const uint32_t* __restrict__ pk0, const uint32_t* __restrict__ pk1,
    const uint32_t* __restrict__ pk2,
    const float* __restrict__ b0, const float* __restrict__ b1, const float* __restrict__ b2,
    float* __restrict__ out, int M, int nsrc, int donorm, int act,
    unsigned int* __restrict__ pool)
{
    extern __shared__ char smem[];
    float* bias_s = (float*)smem;
    float* inv_s  = (float*)(smem + 512);
    uint32_t stiles = (uint32_t)__cvta_generic_to_shared(smem) + 1024;

    int t = threadIdx.x;
    int lane = t & 31, wid = t >> 5;
    int warpm = wid >> 2, warpn = wid & 3;
    int gid = lane >> 2, tig = lane & 3;
    int row0 = blockIdx.x * 128;

    if (t < D) {
        float bb = b0[t];
        if (nsrc == 3) bb += b1[t] + b2[t];
        bias_s[t] = bb;
    }

    // thread-constant ldmatrix byte offsets (stride 20 u32 = 80 B per row)
    int arow = warpm * 64 + (lane & 7) + ((lane >> 3) & 1) * 8;
    uint32_t aoff = (uint32_t)(arow * 80) + (lane >> 4) * 16;
    int nrow = warpn * 32 + (lane & 7) + (lane >> 4) * 8;
    uint32_t boff = (uint32_t)(nrow * 80) + ((lane >> 3) & 1) * 16;

    // A loader mapping: 4 float4 per thread
    int ar = t >> 3;        // rows ar, ar+32, ar+64, ar+96
    int aj = t & 7;         // float4 index within 32-float row

    float acc[4][4][4];
#pragma unroll
    for (int i = 0; i < 4; i++)
#pragma unroll
        for (int j = 0; j < 4; j++)
#pragma unroll
            for (int k = 0; k < 4; k++) acc[i][j][k] = 0.f;

    const float* xs[3] = { x0, x1, x2 };
    const uint32_t* ps[3] = { pk0, pk1, pk2 };
    const int nch = nsrc * 4;

    float4 av[4];

    // ---- prologue: chunk 0 into stage 0 ----------------------------------------
    {
        const float* src = xs[0];
#pragma unroll
        for (int h = 0; h < 4; h++) {
            int r = ar + h * 32;
            av[h] = make_float4(0.f, 0.f, 0.f, 0.f);
            if (row0 + r < M)
                av[h] = *(const float4*)(src + (size_t)(row0 + r) * D + aj * 4);
        }
        const uint32_t* sH = ps[0];
        const uint32_t* sL = ps[0] + 8192;
        uint32_t dH = stiles + 20480, dL = stiles + 30720;
#pragma unroll
        for (int i = 0; i < 2; i++) {
            int idx = t + i * 256;
            int n = idx >> 2, j4 = idx & 3;
            cp16(dH + n * 80 + j4 * 16, sH + n * 64 + j4 * 4);
            cp16(dL + n * 80 + j4 * 16, sL + n * 64 + j4 * 4);
        }
        CP_COMMIT();
        uint32_t* pH = (uint32_t*)(smem + 1024);
        uint32_t* pL = (uint32_t*)(smem + 1024 + 10240);
#pragma unroll
        for (int h = 0; h < 4; h++) {
            int r = ar + h * 32;
            float4 v = av[h];
            uint32_t h0 = packbf(v.y, v.x), h1 = packbf(v.w, v.z);
            float r0 = v.x - bf_lo(h0), r1 = v.y - bf_hi(h0);
            float r2 = v.z - bf_lo(h1), r3 = v.w - bf_hi(h1);
            *(uint2*)(pH + r * 20 + aj * 2) = make_uint2(h0, h1);
            *(uint2*)(pL + r * 20 + aj * 2) = make_uint2(packbf(r1, r0), packbf(r3, r2));
        }
        CP_WAIT0();
    }
    __syncthreads();

    // ---- main pipelined loop ----------------------------------------------------
    for (int c = 0; c < nch; c++) {
        int s = c & 1;
        int have_next = (c + 1 < nch);

        if (have_next) {
            int c1 = c + 1;
            const float* src = xs[c1 >> 2];
            int kofs = (c1 & 3) * 32;
#pragma unroll
            for (int h = 0; h < 4; h++) {
                int r = ar + h * 32;
                av[h] = make_float4(0.f, 0.f, 0.f, 0.f);
                if (row0 + r < M)
                    av[h] = *(const float4*)(src + (size_t)(row0 + r) * D + kofs + aj * 4);
            }
            const uint32_t* pk = ps[c1 >> 2];
            int k2o = (c1 & 3) * 16;
            const uint32_t* sH = pk + k2o;
            const uint32_t* sL = pk + 8192 + k2o;
            uint32_t sb = stiles + (s ^ 1) * STG_BYTES;
            uint32_t dH = sb + 20480, dL = sb + 30720;
#pragma unroll
            for (int i = 0; i < 2; i++) {
                int idx = t + i * 256;
                int n = idx >> 2, j4 = idx & 3;
                cp16(dH + n * 80 + j4 * 16, sH + n * 64 + j4 * 4);
                cp16(dL + n * 80 + j4 * 16, sL + n * 64 + j4 * 4);
            }
            CP_COMMIT();
        }

        // ---- MMA on stage s via ldmatrix ----------------------------------------
        {
            uint32_t bAH = stiles + s * STG_BYTES;
            uint32_t bAL = bAH + 10240;
            uint32_t bBH = bAH + 20480;
            uint32_t bBL = bAH + 30720;
#pragma unroll
            for (int ks = 0; ks < 2; ks++) {
                uint32_t kso = ks * 32;
                uint32_t bh[4][2], bl[4][2], r4[4];
#pragma unroll
                for (int p = 0; p < 2; p++) {
                    ldm4(r4, bBH + boff + p * 1280 + kso);
                    bh[2 * p][0] = r4[0]; bh[2 * p][1] = r4[1];
                    bh[2 * p + 1][0] = r4[2]; bh[2 * p + 1][1] = r4[3];
                    ldm4(r4, bBL + boff + p * 1280 + kso);
                    bl[2 * p][0] = r4[0]; bl[2 * p][1] = r4[1];
                    bl[2 * p + 1][0] = r4[2]; bl[2 * p + 1][1] = r4[3];
                }
#pragma unroll
                for (int mf = 0; mf < 4; mf++) {
                    uint32_t ah[4], al[4];
                    ldm4(ah, bAH + aoff + mf * 1280 + kso);
                    ldm4(al, bAL + aoff + mf * 1280 + kso);
#pragma unroll
                    for (int nf = 0; nf < 4; nf++) {
                        mma16(acc[mf][nf], ah[0], ah[1], ah[2], ah[3], bh[nf][0], bh[nf][1]);
                        mma16(acc[mf][nf], ah[0], ah[1], ah[2], ah[3], bl[nf][0], bl[nf][1]);
                        mma16(acc[mf][nf], al[0], al[1], al[2], al[3], bh[nf][0], bh[nf][1]);
                    }
                }
            }
        }

        if (have_next) {
            uint32_t* pH = (uint32_t*)(smem + 1024 + (s ^ 1) * STG_BYTES);
            uint32_t* pL = pH + 2560;
#pragma unroll
            for (int h = 0; h < 4; h++) {
                int r = ar + h * 32;
                float4 v = av[h];
                uint32_t h0 = packbf(v.y, v.x), h1 = packbf(v.w, v.z);
                float r0 = v.x - bf_lo(h0), r1 = v.y - bf_hi(h0);
                float r2 = v.z - bf_lo(h1), r3 = v.w - bf_hi(h1);
                *(uint2*)(pH + r * 20 + aj * 2) = make_uint2(h0, h1);
                *(uint2*)(pL + r * 20 + aj * 2) = make_uint2(packbf(r1, r0), packbf(r3, r2));
            }
            CP_WAIT0();
        }
        __syncthreads();
    }

    // ---- epilogue: stage acc + bias into smem (aliases operand tiles) ----------
    float* stg = (float*)(smem + 1024);                // 128 x 132 floats
#pragma unroll
    for (int mf = 0; mf < 4; mf++) {
        int row = warpm * 64 + mf * 16 + gid;
#pragma unroll
        for (int nf = 0; nf < 4; nf++) {
            int col = warpn * 32 + nf * 8 + 2 * tig;
            stg[row * 132 + col]           = acc[mf][nf][0] + bias_s[col];
            stg[row * 132 + col + 1]       = acc[mf][nf][1] + bias_s[col + 1];
            stg[(row + 8) * 132 + col]     = acc[mf][nf][2] + bias_s[col];
            stg[(row + 8) * 132 + col + 1] = acc[mf][nf][3] + bias_s[col + 1];
        }
    }
    __syncthreads();

    // ---- pass1: per-row inverse L2 norm ----------------------------------------
    if (donorm && t < 128) {
        float ssq = 0.f;
#pragma unroll
        for (int j = 0; j < 32; j++) {
            float4 v = *(float4*)(stg + t * 132 + j * 4);
            ssq += v.x * v.x + v.y * v.y + v.z * v.z + v.w * v.w;
        }
        inv_s[t] = 1.0f / fmaxf(sqrtf(ssq), 1e-12f);
    }
    __syncthreads();

    // ---- pass2: normalize/act, coalesced store, fused column max-pool ----------
    int s = t & 31;
    float4 pmax = make_float4(-3.402823466e38f, -3.402823466e38f,
                              -3.402823466e38f, -3.402823466e38f);
#pragma unroll
    for (int h = 0; h < 16; h++) {
        int idx = t + h * 256;
        int row = idx >> 5;
        float4 v = *(float4*)(stg + row * 132 + s * 4);
        if (donorm) {
            float iv = inv_s[row];
            v.x *= iv; v.y *= iv; v.z *= iv; v.w *= iv;
            if (act) {
                v.x = (v.x >= 0.f) ? v.x : 0.01f * v.x;
                v.y = (v.y >= 0.f) ? v.y : 0.01f * v.y;
                v.z = (v.z >= 0.f) ? v.z : 0.01f * v.z;
                v.w = (v.w >= 0.f) ? v.w : 0.01f * v.w;
            }
        }
        if (row0 + row < M) {
            *(float4*)(out + (size_t)(row0 + row) * D + s * 4) = v;
            if (pool) {
                pmax.x = fmaxf(pmax.x, v.x); pmax.y = fmaxf(pmax.y, v.y);
                pmax.z = fmaxf(pmax.z, v.z); pmax.w = fmaxf(pmax.w, v.w);
            }
        }
    }
    if (pool) {
        float pv[4] = { pmax.x, pmax.y, pmax.z, pmax.w };
#pragma unroll
        for (int j = 0; j < 4; j++) {
            unsigned u = __float_as_uint(pv[j]);
            unsigned mono = (u & 0x80000000u) ? ~u : (u | 0x80000000u);
            atomicMax(&pool[s * 4 + j], mono);
        }
    }

    // ---- re-zero consumed aggregation slices (replaces memsets) ----------------
    if (nsrc == 3) {
        float* z1 = const_cast<float*>(x1);
        float* z2 = const_cast<float*>(x2);
        float4 z = make_float4(0.f, 0.f, 0.f, 0.f);
#pragma unroll
        for (int h = 0; h < 16; h++) {
            int idx = t + h * 256;
            int row = idx >> 5, c4 = idx & 31;
            if (row0 + row < M) {
                *((float4*)(z1 + (size_t)(row0 + row) * D) + c4) = z;
                *((float4*)(z2 + (size_t)(row0 + row) * D) + c4) = z;
            }
        }
    }
}

__global__ void pool_combine_k(unsigned int* __restrict__ pool, float* __restrict__ out)
{
    int t = threadIdx.x;  // 128
    unsigned a = pool[t], bmono = pool[t + D];
    float fa = __uint_as_float((a & 0x80000000u) ? (a & 0x7fffffffu) : ~a);
    float fb = __uint_as_float((bmono & 0x80000000u) ? (bmono & 0x7fffffffu) : ~bmono);
    out[t] = fa + fb;
    pool[t] = 0u;          // re-arm for next graph replay
    pool[t + D] = 0u;
}

// --------- one-time stream/event setup (first, uncaptured, call) -----------------
struct AsyncCtx {
    cudaStream_t s1;
    cudaEvent_t evF, evS4, evGE, evJ;
    AsyncCtx() {
        cudaStreamCreateWithFlags(&s1, cudaStreamNonBlocking);
        cudaEventCreateWithFlags(&evF,  cudaEventDisableTiming);
        cudaEventCreateWithFlags(&evS4, cudaEventDisableTiming);
        cudaEventCreateWithFlags(&evGE, cudaEventDisableTiming);
        cudaEventCreateWithFlags(&evJ,  cudaEventDisableTiming);
    }
};

// ---------------------------------- launch ---------------------------------------
extern "C" void kernel_launch(void* const* d_in, const int* in_sizes, int n_in,
                              void* d_out, int out_size)
{
    static AsyncCtx ax;   // created on the uncaptured correctness call

    const float* nf_in = (const float*)d_in[0];
    const float* ef_in = (const float*)d_in[1];
    const float* nWc = (const float*)d_in[2];
    const float* nbc = (const float*)d_in[3];
    const float* nWn = (const float*)d_in[4];
    const float* nbn = (const float*)d_in[5];
    const float* nWe = (const float*)d_in[6];
    const float* nbe = (const float*)d_in[7];
    const float* eWc = (const float*)d_in[8];
    const float* ebc = (const float*)d_in[9];
    const float* eWn = (const float*)d_in[10];
    const float* ebn = (const float*)d_in[11];
    const float* eWe = (const float*)d_in[12];
    const float* ebe = (const float*)d_in[13];
    const float* Wno = (const float*)d_in[14];
    const float* bno = (const float*)d_in[15];
    const float* Weo = (const float*)d_in[16];
    const float* beo = (const float*)d_in[17];
    const int* ei  = (const int*)d_in[18];   // [2, E]
    const int* lei = (const int*)d_in[19];   // [2, L]
    const int* nei = (const int*)d_in[20];   // [E]
    const int* nes = (const int*)d_in[21];   // [E]
    const int* eni = (const int*)d_in[22];   // [L]
    const int* ens = (const int*)d_in[23];   // [L]
    float* outp = (float*)d_out;             // [pooled(128) | tn(N*128) | te(E*128)]

    cudaFuncSetAttribute(tc_gemm_k, cudaFuncAttributeMaxDynamicSharedMemorySize, SM_TOTAL);

    float *nf0, *nf1, *ef0, *ef1, *an, *a1n;
    float *aeP[2], *a1eP[2];
    unsigned int* pool;
    uint32_t* wpk;
    cudaGetSymbolAddress((void**)&nf0, g_nf0);
    cudaGetSymbolAddress((void**)&nf1, g_nf1);
    cudaGetSymbolAddress((void**)&ef0, g_ef0);
    cudaGetSymbolAddress((void**)&ef1, g_ef1);
    cudaGetSymbolAddress((void**)&an,  g_an);
    cudaGetSymbolAddress((void**)&a1n, g_a1n);
    cudaGetSymbolAddress((void**)&aeP[0],  g_ae0);
    cudaGetSymbolAddress((void**)&a1eP[0], g_a1e0);
    cudaGetSymbolAddress((void**)&aeP[1],  g_ae1);
    cudaGetSymbolAddress((void**)&a1eP[1], g_a1e1);
    cudaGetSymbolAddress((void**)&pool, g_pool);
    cudaGetSymbolAddress((void**)&wpk, g_wpk);

    cudaStream_t s0 = 0, s1 = ax.s1;

    // ---- pre-pack weights, then fork s1 off the capturing stream ----------------
    wprep_all_k<<<(20 * 8192 + 255) / 256, 256, 0, s0>>>(nWc, nWn, nWe, eWc, eWn, eWe,
                                                         Wno, Weo, wpk);
    cudaEventRecord(ax.evF, s0);
    cudaStreamWaitEvent(s1, ax.evF, 0);

    float* nf_bufs[2] = { nf0, nf1 };
    float* ef_bufs[2] = { ef0, ef1 };

    const float* nf_cur = nf_in;
    const float* ef_cur = ef_in;

    const int SCAT_BLOCKS = 25000;
    const int NGB = (N_NODES + 127) / 128;   // 391
    const int EGB = (N_EDGES + 127) / 128;   // 6250

    for (int i = 0; i < NL; i++) {
        float* nf_next = nf_bufs[i & 1];
        float* ef_next = ef_bufs[i & 1];
        float* ae  = aeP[i & 1];
        float* a1e = a1eP[i & 1];
        int act = (i < NL - 1);

        // ---- s0: node-gated scatters run DURING previous G_edge ----------------
        // S1: an += nf_cur[ei0] -> ei1        (nf_cur from s0's G_node(i-1))
        scatter_add_k<<<SCAT_BLOCKS, 256, 0, s0>>>(nf_cur, an, ei, ei + N_EDGES, N_EDGES);
        // S4: a1e[p] += nf_cur[eni] -> ens    (ping-pong buffer: zeroed by G_edge(i-2))
        scatter_add_k<<<SCAT_BLOCKS, 256, 0, s0>>>(nf_cur, a1e, eni, ens, N_LINE);
        cudaEventRecord(ax.evS4, s0);

        // ---- edge-gated scatters (need ef_cur = G_edge(i-1) output) ------------
        // S2 on s0: a1n += ef_cur[nei] -> nes
        if (i > 0) cudaStreamWaitEvent(s0, ax.evGE, 0);
        scatter_add_k<<<SCAT_BLOCKS, 256, 0, s0>>>(ef_cur, a1n, nei, nes, N_EDGES);
        // S3 on s1: ae[p] += ef_cur[lei0] -> lei1 (after G_edge(i-1), same stream)
        scatter_add_k<<<SCAT_BLOCKS, 256, 0, s1>>>(ef_cur, ae, lei, lei + N_LINE, N_LINE);

        // G_node (s0): consumes an/a1n (re-zeroes), writes nf_next
        tc_gemm_k<<<NGB, 256, SM_TOTAL, s0>>>(nf_cur, an, a1n,
                                              wpk + (size_t)(0 + i) * 16384,
                                              wpk + (size_t)(3 + i) * 16384,
                                              wpk + (size_t)(6 + i) * 16384,
                                              nbc + i * D, nbn + i * D, nbe + i * D,
                                              nf_next, N_NODES, 3, 1, act, nullptr);

        // G_edge (s1): needs S3 (same stream) + S4 (s0); consumes ae/a1e, writes ef_next
        cudaStreamWaitEvent(s1, ax.evS4, 0);
        tc_gemm_k<<<EGB, 256, SM_TOTAL, s1>>>(ef_cur, ae, a1e,
                                              wpk + (size_t)(9 + i) * 16384,
                                              wpk + (size_t)(12 + i) * 16384,
                                              wpk + (size_t)(15 + i) * 16384,
                                              ebc + i * D, ebn + i * D, ebe + i * D,
                                              ef_next, N_EDGES, 3, 1, act, nullptr);
        cudaEventRecord(ax.evGE, s1);

        nf_cur = nf_next;
        ef_cur = ef_next;
    }

    // ---- output linears + fused max-pool: node out overlaps last G_edge --------
    tc_gemm_k<<<NGB, 256, SM_TOTAL, s0>>>(nf_cur, nullptr, nullptr,
                                          wpk + (size_t)18 * 16384, nullptr, nullptr,
                                          bno, nullptr, nullptr,
                                          outp + D, N_NODES, 1, 0, 0, pool);
    tc_gemm_k<<<EGB, 256, SM_TOTAL, s1>>>(ef_cur, nullptr, nullptr,
                                          wpk + (size_t)19 * 16384, nullptr, nullptr,
                                          beo, nullptr, nullptr,
                                          outp + D + (size_t)N_NODES * D, N_EDGES,
                                          1, 0, 0, pool + D);
    cudaEventRecord(ax.evJ, s1);
    cudaStreamWaitEvent(s0, ax.evJ, 0);     // join s1 back into the capture stream

    pool_combine_k<<<1, 128, 0, s0>>>(pool, outp);
}